// round 15
// baseline (speedup 1.0000x reference)
#include <cuda_runtime.h>
#include <cuda_fp16.h>
#include <cstdint>

#define N_NODES 100000
#define N_EDGES 600000
#define HIDDEN  128
#define ALPHA   0.1f
#define KHOPS   10
#define EDGE_CAP 1000000   // 600k edges + <=3 pad per node
#define NBLK_N  391        // ceil(N_NODES/256)

// ---------------- device scratch (static; no allocation) ----------------
__device__ __half g_h0h [(size_t)N_NODES * HIDDEN];
__device__ __half g_bufA[(size_t)N_NODES * HIDDEN];
__device__ __half g_bufB[(size_t)N_NODES * HIDDEN];
__device__ int    g_cnt     [N_NODES];
__device__ int    g_rowloc  [N_NODES];
__device__ int    g_blocksum[NBLK_N];
__device__ int    g_blockoff[NBLK_N];
__device__ int    g_rowptr  [N_NODES + 1];
__device__ int    g_cursor  [N_NODES];
__device__ float  g_dinv    [N_NODES];
__device__ float  g_selfw   [N_NODES];
__device__ int2   g_edge    [EDGE_CAP];
__device__ int    g_is64;
// grid barrier state (generation-based: correct for any persisted start value)
__device__ volatile unsigned g_sense;
__device__ unsigned          g_count;

// ---------------- fp16 vector helpers ----------------
__device__ __forceinline__ void sth4(__half* p, float4 v) {
    __half2 a = __floats2half2_rn(v.x, v.y);
    __half2 b = __floats2half2_rn(v.z, v.w);
    uint2 raw;
    raw.x = *(unsigned*)&a;
    raw.y = *(unsigned*)&b;
    *(uint2*)p = raw;
}
__device__ __forceinline__ void ldh8(const __half* p, float4& lo, float4& hi) {
    uint4 raw = *(const uint4*)p;
    float2 f0 = __half22float2(*(__half2*)&raw.x);
    float2 f1 = __half22float2(*(__half2*)&raw.y);
    float2 f2 = __half22float2(*(__half2*)&raw.z);
    float2 f3 = __half22float2(*(__half2*)&raw.w);
    lo = make_float4(f0.x, f0.y, f1.x, f1.y);
    hi = make_float4(f2.x, f2.y, f3.x, f3.y);
}
__device__ __forceinline__ void fma8(float4& aL, float4& aH, float w, float4 vL, float4 vH) {
    aL.x += w * vL.x; aL.y += w * vL.y; aL.z += w * vL.z; aL.w += w * vL.w;
    aH.x += w * vH.x; aH.y += w * vH.y; aH.z += w * vH.z; aH.w += w * vH.w;
}
__device__ __forceinline__ unsigned f2h2(float a, float b) {
    __half2 h = __floats2half2_rn(a, b);
    return *(unsigned*)&h;
}

// ---------------- zero cnt + probe (no W conversion anymore) ----------------
__global__ void probe_zero(const int* __restrict__ ei32, int* __restrict__ cnt) {
    int i = blockIdx.x * 256 + threadIdx.x;
    if (i < N_NODES) cnt[i] = 0;
    if (i == 0) {
        g_count = 0;
        int acc = 0;
        for (int k = 0; k < 128; k++) acc |= ei32[2 * k + 1];
        g_is64 = (acc == 0) ? 1 : 0;
    }
}

__device__ __forceinline__ int load_idx(const int* ei32, long long pos, int is64) {
    return is64 ? ei32[2 * pos] : ei32[pos];
}

// ---------------- in-degree count ----------------
__global__ void deg_count(const int* __restrict__ ei32, int* __restrict__ cnt) {
    int e = blockIdx.x * 256 + threadIdx.x;
    if (e < N_EDGES) {
        int d = load_idx(ei32, (long long)N_EDGES + e, g_is64);
        if ((unsigned)d < N_NODES) atomicAdd(&cnt[d], 1);
    }
}

// ---------------- per-block exclusive scan of padded counts ----------------
__global__ __launch_bounds__(256) void scan_block(
    const int* __restrict__ cnt, int* __restrict__ rowloc, int* __restrict__ blocksum)
{
    __shared__ int sh[256];
    int t = threadIdx.x;
    int i = blockIdx.x * 256 + t;
    int c = (i < N_NODES) ? ((cnt[i] + 3) & ~3) : 0;
    sh[t] = c;
    __syncthreads();
    for (int d = 1; d < 256; d <<= 1) {
        int v = (t >= d) ? sh[t - d] : 0;
        __syncthreads();
        sh[t] += v;
        __syncthreads();
    }
    if (i < N_NODES) rowloc[i] = sh[t] - c;
    if (t == 255) blocksum[blockIdx.x] = sh[255];
}

// ---------------- tensor-core GEMM h0 = x @ W^T + b ----------------
// Zero-dependency: reads fp32 W directly, converts to fp16 smem in prologue.
#define WSTRIDE 136
__global__ __launch_bounds__(256) void gemm_hmma(
    const float* __restrict__ x, const float* __restrict__ W,
    const float* __restrict__ b, __half* __restrict__ out)
{
    __shared__ __half Ws[128 * WSTRIDE];
    __shared__ float bs[128];
    const int tid = threadIdx.x;

    // convert W (128x128 fp32, L2-resident) to fp16 smem, padded rows
#pragma unroll
    for (int it = 0; it < 16; it++) {
        int idx = it * 256 + tid;            // float4 index over [128 rows][32 float4]
        int r = idx >> 5, c = (idx & 31) * 4;
        float4 v = ((const float4*)W)[idx];
        sth4(&Ws[r * WSTRIDE + c], v);
    }
    if (tid < 128) bs[tid] = b[tid];
    __syncthreads();

    const int w = tid >> 5, lane = tid & 31;
    const int r  = lane >> 2;
    const int kq = (lane & 3) * 2;
    const int Rbase = blockIdx.x * 128 + w * 16;

    int row0 = Rbase + r;
    int row1 = Rbase + r + 8;
    int row0c = row0 < N_NODES ? row0 : 0;
    int row1c = row1 < N_NODES ? row1 : 0;

    float d[16][4];
#pragma unroll
    for (int nt = 0; nt < 16; nt++)
#pragma unroll
        for (int q = 0; q < 4; q++) d[nt][q] = 0.0f;

    const float* a0p = x + (size_t)row0c * HIDDEN;
    const float* a1p = x + (size_t)row1c * HIDDEN;

    float2 f0 = *(const float2*)(a0p + kq);
    float2 f1 = *(const float2*)(a1p + kq);
    float2 f2 = *(const float2*)(a0p + kq + 8);
    float2 f3 = *(const float2*)(a1p + kq + 8);

#pragma unroll
    for (int ks = 0; ks < 8; ks++) {
        unsigned a0 = f2h2(f0.x, f0.y);
        unsigned a1 = f2h2(f1.x, f1.y);
        unsigned a2 = f2h2(f2.x, f2.y);
        unsigned a3 = f2h2(f3.x, f3.y);
        if (ks < 7) {
            int k0 = (ks + 1) * 16 + kq;
            f0 = *(const float2*)(a0p + k0);
            f1 = *(const float2*)(a1p + k0);
            f2 = *(const float2*)(a0p + k0 + 8);
            f3 = *(const float2*)(a1p + k0 + 8);
        }
#pragma unroll
        for (int nt = 0; nt < 16; nt++) {
            int c = nt * 8 + r;
            unsigned b0 = *(const unsigned*)&Ws[c * WSTRIDE + ks * 16 + kq];
            unsigned b1 = *(const unsigned*)&Ws[c * WSTRIDE + ks * 16 + kq + 8];
            asm volatile(
                "mma.sync.aligned.m16n8k16.row.col.f32.f16.f16.f32 "
                "{%0,%1,%2,%3}, {%4,%5,%6,%7}, {%8,%9}, {%0,%1,%2,%3};"
                : "+f"(d[nt][0]), "+f"(d[nt][1]), "+f"(d[nt][2]), "+f"(d[nt][3])
                : "r"(a0), "r"(a1), "r"(a2), "r"(a3), "r"(b0), "r"(b1));
        }
    }

    const int c0 = (lane & 3) * 2;
#pragma unroll
    for (int nt = 0; nt < 16; nt++) {
        int col = nt * 8 + c0;
        if (row0 < N_NODES) {
            __half2 v = __floats2half2_rn(d[nt][0] + bs[col], d[nt][1] + bs[col + 1]);
            *(__half2*)&out[(size_t)row0 * HIDDEN + col] = v;
        }
        if (row1 < N_NODES) {
            __half2 v = __floats2half2_rn(d[nt][2] + bs[col], d[nt][3] + bs[col + 1]);
            *(__half2*)&out[(size_t)row1 * HIDDEN + col] = v;
        }
    }
}

// ---------------- scan of 391 block sums ----------------
__global__ __launch_bounds__(512) void scan_top(
    const int* __restrict__ blocksum, int* __restrict__ blockoff)
{
    __shared__ int sh[512];
    int t = threadIdx.x;
    int v = (t < NBLK_N) ? blocksum[t] : 0;
    sh[t] = v;
    __syncthreads();
    for (int d = 1; d < 512; d <<= 1) {
        int u = (t >= d) ? sh[t - d] : 0;
        __syncthreads();
        sh[t] += u;
        __syncthreads();
    }
    if (t < NBLK_N) blockoff[t] = sh[t] - v;
}

// ---------------- apply offsets + node prep + write pad slots ----------------
__global__ void prep_apply(const int* __restrict__ cnt, const int* __restrict__ rowloc,
                           const int* __restrict__ blockoff,
                           int* __restrict__ row_ptr, int* __restrict__ cursor,
                           float* __restrict__ dinv, float* __restrict__ selfw,
                           int2* __restrict__ edge)
{
    int i = blockIdx.x * 256 + threadIdx.x;
    if (i < N_NODES) {
        int c = cnt[i];
        int pad = (c + 3) & ~3;
        int beg = rowloc[i] + blockoff[blockIdx.x];
        row_ptr[i] = beg;
        cursor[i]  = beg;
        for (int k = c; k < pad; k++) edge[beg + k] = make_int2(0, 0);
        float r = rsqrtf((float)c + 1.0f);
        dinv[i]  = r;
        selfw[i] = (1.0f - ALPHA) * r * r;
        if (i == N_NODES - 1) row_ptr[N_NODES] = beg + pad;
    }
}

// ---------------- CSR edge placement ----------------
__global__ void edge_place(const int* __restrict__ ei32, const float* __restrict__ dinv,
                           int* __restrict__ cursor, int2* __restrict__ edge)
{
    int e = blockIdx.x * 256 + threadIdx.x;
    if (e < N_EDGES) {
        int is64 = g_is64;
        int s = load_idx(ei32, e, is64);
        int d = load_idx(ei32, (long long)N_EDGES + e, is64);
        if ((unsigned)s >= N_NODES) s = 0;
        if ((unsigned)d >= N_NODES) d = 0;
        int pos = atomicAdd(&cursor[d], 1);
        float w = (1.0f - ALPHA) * dinv[s] * dinv[d];
        edge[pos] = make_int2(s, __float_as_int(w));
    }
}

// ---------------- flat grid barrier (sense-reversing, generation-based) ----------------
__device__ __forceinline__ void grid_bar(int nblocks) {
    __syncthreads();
    if (threadIdx.x == 0) {
        __threadfence();                       // release this block's stores
        unsigned gen = g_sense;
        unsigned t = atomicAdd(&g_count, 1u);
        if (t == (unsigned)nblocks - 1) {
            atomicExch(&g_count, 0u);
            __threadfence();
            g_sense = gen + 1;
        } else {
            while (g_sense == gen) __nanosleep(64);
        }
        __threadfence();                       // acquire
    }
    __syncthreads();
}

// ---------------- one-hop body ----------------
// FIRST: cur == h0, fold alpha*h0 into the self term (skip one 25.6MB read)
template <bool FIRST, bool FINAL>
__device__ __forceinline__ void prop_group(
    int n, int l, const __half* __restrict__ cur, const __half* __restrict__ h0,
    const float* __restrict__ selfw, const int* __restrict__ row_ptr,
    const int2* __restrict__ edge, void* __restrict__ outp)
{
    const size_t off = (size_t)n * HIDDEN + l * 8;
    float4 svL, svH;
    ldh8(cur + off, svL, svH);
    float sw = selfw[n];

    float4 aL, aH;
    if (FIRST) {
        float c = ALPHA + sw;   // cur == h0 on hop 0
        aL.x = c * svL.x;  aL.y = c * svL.y;  aL.z = c * svL.z;  aL.w = c * svL.w;
        aH.x = c * svH.x;  aH.y = c * svH.y;  aH.z = c * svH.z;  aH.w = c * svH.w;
    } else {
        float4 h0L, h0H;
        ldh8(h0 + off, h0L, h0H);
        aL.x = ALPHA * h0L.x + sw * svL.x;  aL.y = ALPHA * h0L.y + sw * svL.y;
        aL.z = ALPHA * h0L.z + sw * svL.z;  aL.w = ALPHA * h0L.w + sw * svL.w;
        aH.x = ALPHA * h0H.x + sw * svH.x;  aH.y = ALPHA * h0H.y + sw * svH.y;
        aH.z = ALPHA * h0H.z + sw * svH.z;  aH.w = ALPHA * h0H.w + sw * svH.w;
    }

    int beg = __ldg(row_ptr + n);
    int end = __ldg(row_ptr + n + 1);   // padded end; pads = {0, 0.0f}
    for (int j = beg; j < end; j += 4) {
        const int4* ep = (const int4*)(edge + j);
        int4 E0 = __ldg(ep);
        int4 E1 = __ldg(ep + 1);
        float4 v0L,v0H,v1L,v1H,v2L,v2H,v3L,v3H;
        ldh8(cur + (size_t)E0.x * HIDDEN + l * 8, v0L, v0H);
        ldh8(cur + (size_t)E0.z * HIDDEN + l * 8, v1L, v1H);
        ldh8(cur + (size_t)E1.x * HIDDEN + l * 8, v2L, v2H);
        ldh8(cur + (size_t)E1.z * HIDDEN + l * 8, v3L, v3H);
        fma8(aL, aH, __int_as_float(E0.y), v0L, v0H);
        fma8(aL, aH, __int_as_float(E0.w), v1L, v1H);
        fma8(aL, aH, __int_as_float(E1.y), v2L, v2H);
        fma8(aL, aH, __int_as_float(E1.w), v3L, v3H);
    }

    if (FINAL) {
        float* o = (float*)outp + off;
        *(float4*)o       = aL;
        *(float4*)(o + 4) = aH;
    } else {
        __half* o = (__half*)outp + off;
        sth4(o, aL);
        sth4(o + 4, aH);
    }
}

// ---------------- persistent prop: all KHOPS in one launch ----------------
__global__ __launch_bounds__(256) void prop_persist(
    const __half* __restrict__ h0, __half* __restrict__ bufA, __half* __restrict__ bufB,
    const float* __restrict__ selfw, const int* __restrict__ row_ptr,
    const int2* __restrict__ edge, float* __restrict__ out, int nblocks)
{
    const int NLANES = N_NODES * 16;
    const int stride = nblocks * 256;
    int base = blockIdx.x * 256 + threadIdx.x;

    for (int hop = 0; hop < KHOPS; hop++) {
        const __half* cur = (hop == 0) ? h0 : ((hop & 1) ? bufA : bufB);
        for (int gtid = base; gtid < NLANES; gtid += stride) {
            int n = gtid >> 4, l = gtid & 15;
            if (hop == 0)
                prop_group<true, false>(n, l, cur, h0, selfw, row_ptr, edge, bufA);
            else if (hop == KHOPS - 1)
                prop_group<false, true >(n, l, cur, h0, selfw, row_ptr, edge, out);
            else
                prop_group<false, false>(n, l, cur, h0, selfw, row_ptr, edge,
                                         (hop & 1) ? bufB : bufA);
        }
        if (hop < KHOPS - 1) grid_bar(nblocks);
    }
}

// ---------------- fallback per-hop kernel ----------------
template <bool FIRST, bool FINAL>
__global__ __launch_bounds__(256) void prop_kernel(
    const __half* __restrict__ cur, const __half* __restrict__ h0,
    const float* __restrict__ selfw,
    const int* __restrict__ row_ptr, const int2* __restrict__ edge,
    void* __restrict__ outp)
{
    int gtid = blockIdx.x * 256 + threadIdx.x;
    int n = gtid >> 4, l = gtid & 15;
    if (n >= N_NODES) return;
    prop_group<FIRST, FINAL>(n, l, cur, h0, selfw, row_ptr, edge, outp);
}

// ---------------- launch ----------------
extern "C" void kernel_launch(void* const* d_in, const int* in_sizes, int n_in,
                              void* d_out, int out_size)
{
    const float* x    = (const float*)d_in[0];
    const int*   ei32 = (const int*)d_in[1];
    const float* W    = (const float*)d_in[2];
    const float* b    = (const float*)d_in[3];
    float* out = (float*)d_out;

    __half *h0h, *bufA, *bufB;
    float *dinv, *selfw;
    int *cnt, *rowloc, *blocksum, *blockoff, *row_ptr, *cursor;
    int2 *edge;
    cudaGetSymbolAddress((void**)&h0h,      g_h0h);
    cudaGetSymbolAddress((void**)&bufA,     g_bufA);
    cudaGetSymbolAddress((void**)&bufB,     g_bufB);
    cudaGetSymbolAddress((void**)&cnt,      g_cnt);
    cudaGetSymbolAddress((void**)&rowloc,   g_rowloc);
    cudaGetSymbolAddress((void**)&blocksum, g_blocksum);
    cudaGetSymbolAddress((void**)&blockoff, g_blockoff);
    cudaGetSymbolAddress((void**)&row_ptr,  g_rowptr);
    cudaGetSymbolAddress((void**)&cursor,   g_cursor);
    cudaGetSymbolAddress((void**)&dinv,     g_dinv);
    cudaGetSymbolAddress((void**)&selfw,    g_selfw);
    cudaGetSymbolAddress((void**)&edge,     g_edge);

    const int NB_E = (N_EDGES + 255) / 256;   // 2344
    const int NB_G = (N_NODES + 127) / 128;   // 782

    cudaStream_t s2;
    cudaEvent_t evFork, evJoin;
    cudaStreamCreateWithFlags(&s2, cudaStreamNonBlocking);
    cudaEventCreateWithFlags(&evFork, cudaEventDisableTiming);
    cudaEventCreateWithFlags(&evJoin, cudaEventDisableTiming);

    // fork FIRST: GEMM has zero dependencies now (reads fp32 W directly)
    cudaEventRecord(evFork, 0);
    cudaStreamWaitEvent(s2, evFork, 0);
    gemm_hmma<<<NB_G, 256, 0, s2>>>(x, W, b, h0h);

    // CSR build chain on the main stream, fully parallel with the GEMM
    probe_zero<<<NBLK_N, 256>>>(ei32, cnt);
    deg_count <<<NB_E, 256>>>(ei32, cnt);
    scan_block<<<NBLK_N, 256>>>(cnt, rowloc, blocksum);
    scan_top  <<<1, 512>>>(blocksum, blockoff);
    prep_apply<<<NBLK_N, 256>>>(cnt, rowloc, blockoff, row_ptr, cursor,
                                dinv, selfw, edge);
    edge_place<<<NB_E, 256>>>(ei32, dinv, cursor, edge);

    cudaEventRecord(evJoin, s2);
    cudaStreamWaitEvent(0, evJoin, 0);

    // persistent prop sized to guaranteed co-residency
    int perSM = 0, sms = 0, dev = 0;
    cudaGetDevice(&dev);
    cudaDeviceGetAttribute(&sms, cudaDevAttrMultiProcessorCount, dev);
    cudaOccupancyMaxActiveBlocksPerMultiprocessor(&perSM, prop_persist, 256, 0);

    if (perSM > 0 && sms > 0) {
        int nblocks = perSM * sms;
        const int maxblocks = (N_NODES * 16 + 255) / 256;  // no more than the work
        if (nblocks > maxblocks) nblocks = maxblocks;
        prop_persist<<<nblocks, 256>>>(h0h, bufA, bufB, selfw, row_ptr, edge, out, nblocks);
    } else {
        const int NB_PROP = (N_NODES * 16 + 255) / 256;
        const __half* cur = h0h;
        for (int hop = 0; hop < KHOPS; hop++) {
            if (hop == 0) {
                prop_kernel<true, false><<<NB_PROP, 256>>>(cur, h0h, selfw, row_ptr, edge, bufA);
                cur = bufA;
            } else if (hop == KHOPS - 1) {
                prop_kernel<false, true><<<NB_PROP, 256>>>(cur, h0h, selfw, row_ptr, edge, out);
            } else {
                __half* nxt = (hop & 1) ? bufB : bufA;
                prop_kernel<false, false><<<NB_PROP, 256>>>(cur, h0h, selfw, row_ptr, edge, nxt);
                cur = nxt;
            }
        }
    }
}

// round 16
// speedup vs baseline: 1.0012x; 1.0012x over previous
#include <cuda_runtime.h>
#include <cuda_fp16.h>
#include <cstdint>

#define N_NODES 100000
#define N_EDGES 600000
#define HIDDEN  128
#define ALPHA   0.1f
#define KHOPS   10
#define EDGE_CAP 1000000   // 600k edges + <=3 pad per node
#define NBLK_N  391        // ceil(N_NODES/256)

// ---------------- device scratch (static; no allocation) ----------------
__device__ __half g_Wh  [HIDDEN * HIDDEN];
__device__ __half g_h0h [(size_t)N_NODES * HIDDEN];
__device__ __half g_bufA[(size_t)N_NODES * HIDDEN];
__device__ __half g_bufB[(size_t)N_NODES * HIDDEN];
__device__ int    g_cnt     [N_NODES];
__device__ int    g_rowloc  [N_NODES];
__device__ int    g_blocksum[NBLK_N];
__device__ int    g_blockoff[NBLK_N];
__device__ int    g_rowptr  [N_NODES + 1];
__device__ int    g_cursor  [N_NODES];
__device__ float  g_dinv    [N_NODES];
__device__ float  g_selfw   [N_NODES];
__device__ int2   g_edge    [EDGE_CAP];
__device__ int    g_is64;
// grid barrier state (generation-based: correct for any persisted start value)
__device__ volatile unsigned g_sense;
__device__ unsigned          g_count;

// ---------------- fp16 vector helpers ----------------
__device__ __forceinline__ void sth4(__half* p, float4 v) {
    __half2 a = __floats2half2_rn(v.x, v.y);
    __half2 b = __floats2half2_rn(v.z, v.w);
    uint2 raw;
    raw.x = *(unsigned*)&a;
    raw.y = *(unsigned*)&b;
    *(uint2*)p = raw;
}
__device__ __forceinline__ void ldh8(const __half* p, float4& lo, float4& hi) {
    uint4 raw = *(const uint4*)p;
    float2 f0 = __half22float2(*(__half2*)&raw.x);
    float2 f1 = __half22float2(*(__half2*)&raw.y);
    float2 f2 = __half22float2(*(__half2*)&raw.z);
    float2 f3 = __half22float2(*(__half2*)&raw.w);
    lo = make_float4(f0.x, f0.y, f1.x, f1.y);
    hi = make_float4(f2.x, f2.y, f3.x, f3.y);
}
__device__ __forceinline__ void fma8(float4& aL, float4& aH, float w, float4 vL, float4 vH) {
    aL.x += w * vL.x; aL.y += w * vL.y; aL.z += w * vL.z; aL.w += w * vL.w;
    aH.x += w * vH.x; aH.y += w * vH.y; aH.z += w * vH.z; aH.w += w * vH.w;
}
__device__ __forceinline__ unsigned f2h2(float a, float b) {
    __half2 h = __floats2half2_rn(a, b);
    return *(unsigned*)&h;
}

// ---------------- zero cnt + convert W + probe ----------------
__global__ void probe_zero(const int* __restrict__ ei32, const float* __restrict__ W,
                           int* __restrict__ cnt, __half* __restrict__ Wh) {
    int i = blockIdx.x * 256 + threadIdx.x;
    if (i < N_NODES) cnt[i] = 0;
    if (i < HIDDEN * HIDDEN / 4) {
        float4 v = ((const float4*)W)[i];
        sth4(Wh + (size_t)i * 4, v);
    }
    if (i == 0) {
        g_count = 0;
        int acc = 0;
        for (int k = 0; k < 128; k++) acc |= ei32[2 * k + 1];
        g_is64 = (acc == 0) ? 1 : 0;
    }
}

__device__ __forceinline__ int load_idx(const int* ei32, long long pos, int is64) {
    return is64 ? ei32[2 * pos] : ei32[pos];
}

// ---------------- in-degree count ----------------
__global__ void deg_count(const int* __restrict__ ei32, int* __restrict__ cnt) {
    int e = blockIdx.x * 256 + threadIdx.x;
    if (e < N_EDGES) {
        int d = load_idx(ei32, (long long)N_EDGES + e, g_is64);
        if ((unsigned)d < N_NODES) atomicAdd(&cnt[d], 1);
    }
}

// ---------------- per-block exclusive scan of padded counts ----------------
__global__ __launch_bounds__(256) void scan_block(
    const int* __restrict__ cnt, int* __restrict__ rowloc, int* __restrict__ blocksum)
{
    __shared__ int sh[256];
    int t = threadIdx.x;
    int i = blockIdx.x * 256 + t;
    int c = (i < N_NODES) ? ((cnt[i] + 3) & ~3) : 0;
    sh[t] = c;
    __syncthreads();
    for (int d = 1; d < 256; d <<= 1) {
        int v = (t >= d) ? sh[t - d] : 0;
        __syncthreads();
        sh[t] += v;
        __syncthreads();
    }
    if (i < N_NODES) rowloc[i] = sh[t] - c;
    if (t == 255) blocksum[blockIdx.x] = sh[255];
}

// ---------------- tensor-core GEMM h0 = x @ W^T + b (overlapped branch) ----------------
#define WSTRIDE 136
__global__ __launch_bounds__(256) void gemm_hmma(
    const float* __restrict__ x, const __half* __restrict__ Wh,
    const float* __restrict__ b, __half* __restrict__ out)
{
    __shared__ __half Ws[128 * WSTRIDE];
    __shared__ float bs[128];
    const int tid = threadIdx.x;

#pragma unroll
    for (int it = 0; it < 8; it++) {
        int idx = it * 256 + tid;
        int r = idx >> 4, c = (idx & 15) * 8;
        *(uint4*)&Ws[r * WSTRIDE + c] = ((const uint4*)Wh)[idx];
    }
    if (tid < 128) bs[tid] = b[tid];
    __syncthreads();

    const int w = tid >> 5, lane = tid & 31;
    const int r  = lane >> 2;
    const int kq = (lane & 3) * 2;
    const int Rbase = blockIdx.x * 128 + w * 16;

    int row0 = Rbase + r;
    int row1 = Rbase + r + 8;
    int row0c = row0 < N_NODES ? row0 : 0;
    int row1c = row1 < N_NODES ? row1 : 0;

    float d[16][4];
#pragma unroll
    for (int nt = 0; nt < 16; nt++)
#pragma unroll
        for (int q = 0; q < 4; q++) d[nt][q] = 0.0f;

    const float* a0p = x + (size_t)row0c * HIDDEN;
    const float* a1p = x + (size_t)row1c * HIDDEN;

    float2 f0 = *(const float2*)(a0p + kq);
    float2 f1 = *(const float2*)(a1p + kq);
    float2 f2 = *(const float2*)(a0p + kq + 8);
    float2 f3 = *(const float2*)(a1p + kq + 8);

#pragma unroll
    for (int ks = 0; ks < 8; ks++) {
        unsigned a0 = f2h2(f0.x, f0.y);
        unsigned a1 = f2h2(f1.x, f1.y);
        unsigned a2 = f2h2(f2.x, f2.y);
        unsigned a3 = f2h2(f3.x, f3.y);
        if (ks < 7) {
            int k0 = (ks + 1) * 16 + kq;
            f0 = *(const float2*)(a0p + k0);
            f1 = *(const float2*)(a1p + k0);
            f2 = *(const float2*)(a0p + k0 + 8);
            f3 = *(const float2*)(a1p + k0 + 8);
        }
#pragma unroll
        for (int nt = 0; nt < 16; nt++) {
            int c = nt * 8 + r;
            unsigned b0 = *(const unsigned*)&Ws[c * WSTRIDE + ks * 16 + kq];
            unsigned b1 = *(const unsigned*)&Ws[c * WSTRIDE + ks * 16 + kq + 8];
            asm volatile(
                "mma.sync.aligned.m16n8k16.row.col.f32.f16.f16.f32 "
                "{%0,%1,%2,%3}, {%4,%5,%6,%7}, {%8,%9}, {%0,%1,%2,%3};"
                : "+f"(d[nt][0]), "+f"(d[nt][1]), "+f"(d[nt][2]), "+f"(d[nt][3])
                : "r"(a0), "r"(a1), "r"(a2), "r"(a3), "r"(b0), "r"(b1));
        }
    }

    const int c0 = (lane & 3) * 2;
#pragma unroll
    for (int nt = 0; nt < 16; nt++) {
        int col = nt * 8 + c0;
        if (row0 < N_NODES) {
            __half2 v = __floats2half2_rn(d[nt][0] + bs[col], d[nt][1] + bs[col + 1]);
            *(__half2*)&out[(size_t)row0 * HIDDEN + col] = v;
        }
        if (row1 < N_NODES) {
            __half2 v = __floats2half2_rn(d[nt][2] + bs[col], d[nt][3] + bs[col + 1]);
            *(__half2*)&out[(size_t)row1 * HIDDEN + col] = v;
        }
    }
}

// ---------------- scan of 391 block sums ----------------
__global__ __launch_bounds__(512) void scan_top(
    const int* __restrict__ blocksum, int* __restrict__ blockoff)
{
    __shared__ int sh[512];
    int t = threadIdx.x;
    int v = (t < NBLK_N) ? blocksum[t] : 0;
    sh[t] = v;
    __syncthreads();
    for (int d = 1; d < 512; d <<= 1) {
        int u = (t >= d) ? sh[t - d] : 0;
        __syncthreads();
        sh[t] += u;
        __syncthreads();
    }
    if (t < NBLK_N) blockoff[t] = sh[t] - v;
}

// ---------------- apply offsets + node prep + write pad slots ----------------
__global__ void prep_apply(const int* __restrict__ cnt, const int* __restrict__ rowloc,
                           const int* __restrict__ blockoff,
                           int* __restrict__ row_ptr, int* __restrict__ cursor,
                           float* __restrict__ dinv, float* __restrict__ selfw,
                           int2* __restrict__ edge)
{
    int i = blockIdx.x * 256 + threadIdx.x;
    if (i < N_NODES) {
        int c = cnt[i];
        int pad = (c + 3) & ~3;
        int beg = rowloc[i] + blockoff[blockIdx.x];
        row_ptr[i] = beg;
        cursor[i]  = beg;
        for (int k = c; k < pad; k++) edge[beg + k] = make_int2(0, 0);
        float r = rsqrtf((float)c + 1.0f);
        dinv[i]  = r;
        selfw[i] = (1.0f - ALPHA) * r * r;
        if (i == N_NODES - 1) row_ptr[N_NODES] = beg + pad;
    }
}

// ---------------- CSR edge placement ----------------
__global__ void edge_place(const int* __restrict__ ei32, const float* __restrict__ dinv,
                           int* __restrict__ cursor, int2* __restrict__ edge)
{
    int e = blockIdx.x * 256 + threadIdx.x;
    if (e < N_EDGES) {
        int is64 = g_is64;
        int s = load_idx(ei32, e, is64);
        int d = load_idx(ei32, (long long)N_EDGES + e, is64);
        if ((unsigned)s >= N_NODES) s = 0;
        if ((unsigned)d >= N_NODES) d = 0;
        int pos = atomicAdd(&cursor[d], 1);
        float w = (1.0f - ALPHA) * dinv[s] * dinv[d];
        edge[pos] = make_int2(s, __float_as_int(w));
    }
}

// ---------------- flat grid barrier (sense-reversing, generation-based) ----------------
__device__ __forceinline__ void grid_bar(int nblocks) {
    __syncthreads();
    if (threadIdx.x == 0) {
        __threadfence();                       // release this block's stores
        unsigned gen = g_sense;
        unsigned t = atomicAdd(&g_count, 1u);
        if (t == (unsigned)nblocks - 1) {
            g_count = 0;                       // safe: re-arrival gated by sense flip
            __threadfence();
            g_sense = gen + 1;
        } else {
            while (g_sense == gen) __nanosleep(32);
        }
        __threadfence();                       // acquire
    }
    __syncthreads();
}

// ---------------- one-hop body ----------------
// FIRST: cur == h0, fold alpha*h0 into the self term (skip one 25.6MB read)
template <bool FIRST, bool FINAL>
__device__ __forceinline__ void prop_group(
    int n, int l, const __half* __restrict__ cur, const __half* __restrict__ h0,
    const float* __restrict__ selfw, const int* __restrict__ row_ptr,
    const int2* __restrict__ edge, void* __restrict__ outp)
{
    const size_t off = (size_t)n * HIDDEN + l * 8;
    float4 svL, svH;
    ldh8(cur + off, svL, svH);
    float sw = selfw[n];

    float4 aL, aH;
    if (FIRST) {
        float c = ALPHA + sw;   // cur == h0 on hop 0
        aL.x = c * svL.x;  aL.y = c * svL.y;  aL.z = c * svL.z;  aL.w = c * svL.w;
        aH.x = c * svH.x;  aH.y = c * svH.y;  aH.z = c * svH.z;  aH.w = c * svH.w;
    } else {
        float4 h0L, h0H;
        ldh8(h0 + off, h0L, h0H);
        aL.x = ALPHA * h0L.x + sw * svL.x;  aL.y = ALPHA * h0L.y + sw * svL.y;
        aL.z = ALPHA * h0L.z + sw * svL.z;  aL.w = ALPHA * h0L.w + sw * svL.w;
        aH.x = ALPHA * h0H.x + sw * svH.x;  aH.y = ALPHA * h0H.y + sw * svH.y;
        aH.z = ALPHA * h0H.z + sw * svH.z;  aH.w = ALPHA * h0H.w + sw * svH.w;
    }

    int beg = __ldg(row_ptr + n);
    int end = __ldg(row_ptr + n + 1);   // padded end; pads = {0, 0.0f}
    for (int j = beg; j < end; j += 4) {
        const int4* ep = (const int4*)(edge + j);
        int4 E0 = __ldg(ep);
        int4 E1 = __ldg(ep + 1);
        float4 v0L,v0H,v1L,v1H,v2L,v2H,v3L,v3H;
        ldh8(cur + (size_t)E0.x * HIDDEN + l * 8, v0L, v0H);
        ldh8(cur + (size_t)E0.z * HIDDEN + l * 8, v1L, v1H);
        ldh8(cur + (size_t)E1.x * HIDDEN + l * 8, v2L, v2H);
        ldh8(cur + (size_t)E1.z * HIDDEN + l * 8, v3L, v3H);
        fma8(aL, aH, __int_as_float(E0.y), v0L, v0H);
        fma8(aL, aH, __int_as_float(E0.w), v1L, v1H);
        fma8(aL, aH, __int_as_float(E1.y), v2L, v2H);
        fma8(aL, aH, __int_as_float(E1.w), v3L, v3H);
    }

    if (FINAL) {
        float* o = (float*)outp + off;
        *(float4*)o       = aL;
        *(float4*)(o + 4) = aH;
    } else {
        __half* o = (__half*)outp + off;
        sth4(o, aL);
        sth4(o + 4, aH);
    }
}

// ---------------- persistent prop: all KHOPS in one launch ----------------
__global__ __launch_bounds__(256) void prop_persist(
    const __half* __restrict__ h0, __half* __restrict__ bufA, __half* __restrict__ bufB,
    const float* __restrict__ selfw, const int* __restrict__ row_ptr,
    const int2* __restrict__ edge, float* __restrict__ out, int nblocks)
{
    const int NLANES = N_NODES * 16;
    const int stride = nblocks * 256;
    int base = blockIdx.x * 256 + threadIdx.x;

    for (int hop = 0; hop < KHOPS; hop++) {
        const __half* cur = (hop == 0) ? h0 : ((hop & 1) ? bufA : bufB);
        for (int gtid = base; gtid < NLANES; gtid += stride) {
            int n = gtid >> 4, l = gtid & 15;
            if (hop == 0)
                prop_group<true, false>(n, l, cur, h0, selfw, row_ptr, edge, bufA);
            else if (hop == KHOPS - 1)
                prop_group<false, true >(n, l, cur, h0, selfw, row_ptr, edge, out);
            else
                prop_group<false, false>(n, l, cur, h0, selfw, row_ptr, edge,
                                         (hop & 1) ? bufB : bufA);
        }
        if (hop < KHOPS - 1) grid_bar(nblocks);
    }
}

// ---------------- fallback per-hop kernel ----------------
template <bool FIRST, bool FINAL>
__global__ __launch_bounds__(256) void prop_kernel(
    const __half* __restrict__ cur, const __half* __restrict__ h0,
    const float* __restrict__ selfw,
    const int* __restrict__ row_ptr, const int2* __restrict__ edge,
    void* __restrict__ outp)
{
    int gtid = blockIdx.x * 256 + threadIdx.x;
    int n = gtid >> 4, l = gtid & 15;
    if (n >= N_NODES) return;
    prop_group<FIRST, FINAL>(n, l, cur, h0, selfw, row_ptr, edge, outp);
}

// ---------------- launch ----------------
extern "C" void kernel_launch(void* const* d_in, const int* in_sizes, int n_in,
                              void* d_out, int out_size)
{
    const float* x    = (const float*)d_in[0];
    const int*   ei32 = (const int*)d_in[1];
    const float* W    = (const float*)d_in[2];
    const float* b    = (const float*)d_in[3];
    float* out = (float*)d_out;

    __half *Wh, *h0h, *bufA, *bufB;
    float *dinv, *selfw;
    int *cnt, *rowloc, *blocksum, *blockoff, *row_ptr, *cursor;
    int2 *edge;
    cudaGetSymbolAddress((void**)&Wh,       g_Wh);
    cudaGetSymbolAddress((void**)&h0h,      g_h0h);
    cudaGetSymbolAddress((void**)&bufA,     g_bufA);
    cudaGetSymbolAddress((void**)&bufB,     g_bufB);
    cudaGetSymbolAddress((void**)&cnt,      g_cnt);
    cudaGetSymbolAddress((void**)&rowloc,   g_rowloc);
    cudaGetSymbolAddress((void**)&blocksum, g_blocksum);
    cudaGetSymbolAddress((void**)&blockoff, g_blockoff);
    cudaGetSymbolAddress((void**)&row_ptr,  g_rowptr);
    cudaGetSymbolAddress((void**)&cursor,   g_cursor);
    cudaGetSymbolAddress((void**)&dinv,     g_dinv);
    cudaGetSymbolAddress((void**)&selfw,    g_selfw);
    cudaGetSymbolAddress((void**)&edge,     g_edge);

    const int NB_E = (N_EDGES + 255) / 256;   // 2344
    const int NB_G = (N_NODES + 127) / 128;   // 782

    cudaStream_t s2;
    cudaEvent_t evFork, evJoin;
    cudaStreamCreateWithFlags(&s2, cudaStreamNonBlocking);
    cudaEventCreateWithFlags(&evFork, cudaEventDisableTiming);
    cudaEventCreateWithFlags(&evJoin, cudaEventDisableTiming);

    probe_zero<<<NBLK_N, 256>>>(ei32, W, cnt, Wh);

    // fork: GEMM runs in parallel with the CSR build
    cudaEventRecord(evFork, 0);
    cudaStreamWaitEvent(s2, evFork, 0);
    gemm_hmma<<<NB_G, 256, 0, s2>>>(x, Wh, b, h0h);

    deg_count <<<NB_E, 256>>>(ei32, cnt);
    scan_block<<<NBLK_N, 256>>>(cnt, rowloc, blocksum);
    scan_top  <<<1, 512>>>(blocksum, blockoff);
    prep_apply<<<NBLK_N, 256>>>(cnt, rowloc, blockoff, row_ptr, cursor,
                                dinv, selfw, edge);
    edge_place<<<NB_E, 256>>>(ei32, dinv, cursor, edge);

    cudaEventRecord(evJoin, s2);
    cudaStreamWaitEvent(0, evJoin, 0);

    // persistent prop sized to guaranteed co-residency
    int perSM = 0, sms = 0, dev = 0;
    cudaGetDevice(&dev);
    cudaDeviceGetAttribute(&sms, cudaDevAttrMultiProcessorCount, dev);
    cudaOccupancyMaxActiveBlocksPerMultiprocessor(&perSM, prop_persist, 256, 0);

    if (perSM > 0 && sms > 0) {
        int nblocks = perSM * sms;
        const int maxblocks = (N_NODES * 16 + 255) / 256;  // no more than the work
        if (nblocks > maxblocks) nblocks = maxblocks;
        prop_persist<<<nblocks, 256>>>(h0h, bufA, bufB, selfw, row_ptr, edge, out, nblocks);
    } else {
        const int NB_PROP = (N_NODES * 16 + 255) / 256;
        const __half* cur = h0h;
        for (int hop = 0; hop < KHOPS; hop++) {
            if (hop == 0) {
                prop_kernel<true, false><<<NB_PROP, 256>>>(cur, h0h, selfw, row_ptr, edge, bufA);
                cur = bufA;
            } else if (hop == KHOPS - 1) {
                prop_kernel<false, true><<<NB_PROP, 256>>>(cur, h0h, selfw, row_ptr, edge, out);
            } else {
                __half* nxt = (hop & 1) ? bufB : bufA;
                prop_kernel<false, false><<<NB_PROP, 256>>>(cur, h0h, selfw, row_ptr, edge, nxt);
                cur = nxt;
            }
        }
    }
}

// round 17
// speedup vs baseline: 1.0142x; 1.0130x over previous
#include <cuda_runtime.h>
#include <cuda_fp16.h>
#include <cstdint>

#define N_NODES 100000
#define N_EDGES 600000
#define HIDDEN  128
#define ALPHA   0.1f
#define KHOPS   10
#define EDGE_CAP 1000000   // 600k edges + <=3 pad per node
#define NBLK_N  391        // ceil(N_NODES/256)

// ---------------- device scratch (static; no allocation) ----------------
__device__ __half g_Wh  [HIDDEN * HIDDEN];
__device__ __half g_h0h [(size_t)N_NODES * HIDDEN];
__device__ __half g_bufA[(size_t)N_NODES * HIDDEN];
__device__ __half g_bufB[(size_t)N_NODES * HIDDEN];
__device__ int    g_cnt     [N_NODES];
__device__ int    g_rowloc  [N_NODES];
__device__ int    g_blocksum[NBLK_N];
__device__ int    g_blockoff[NBLK_N];
__device__ int    g_rowptr  [N_NODES + 1];
__device__ int    g_cursor  [N_NODES];
__device__ float  g_dinv    [N_NODES];
__device__ float  g_selfw   [N_NODES];
__device__ int2   g_edge    [EDGE_CAP];
__device__ int    g_is64;
// grid barrier state (generation-based: correct for any persisted start value)
__device__ volatile unsigned g_sense;
__device__ unsigned          g_count;

// ---------------- fp16 vector helpers ----------------
__device__ __forceinline__ void sth4(__half* p, float4 v) {
    __half2 a = __floats2half2_rn(v.x, v.y);
    __half2 b = __floats2half2_rn(v.z, v.w);
    uint2 raw;
    raw.x = *(unsigned*)&a;
    raw.y = *(unsigned*)&b;
    *(uint2*)p = raw;
}
__device__ __forceinline__ void ldh8(const __half* p, float4& lo, float4& hi) {
    uint4 raw = *(const uint4*)p;
    float2 f0 = __half22float2(*(__half2*)&raw.x);
    float2 f1 = __half22float2(*(__half2*)&raw.y);
    float2 f2 = __half22float2(*(__half2*)&raw.z);
    float2 f3 = __half22float2(*(__half2*)&raw.w);
    lo = make_float4(f0.x, f0.y, f1.x, f1.y);
    hi = make_float4(f2.x, f2.y, f3.x, f3.y);
}
__device__ __forceinline__ void fma8(float4& aL, float4& aH, float w, float4 vL, float4 vH) {
    aL.x += w * vL.x; aL.y += w * vL.y; aL.z += w * vL.z; aL.w += w * vL.w;
    aH.x += w * vH.x; aH.y += w * vH.y; aH.z += w * vH.z; aH.w += w * vH.w;
}
__device__ __forceinline__ unsigned f2h2(float a, float b) {
    __half2 h = __floats2half2_rn(a, b);
    return *(unsigned*)&h;
}

// ---------------- zero cnt + convert W + probe ----------------
__global__ void probe_zero(const int* __restrict__ ei32, const float* __restrict__ W,
                           int* __restrict__ cnt, __half* __restrict__ Wh) {
    int i = blockIdx.x * 256 + threadIdx.x;
    if (i < N_NODES) cnt[i] = 0;
    if (i < HIDDEN * HIDDEN / 4) {
        float4 v = ((const float4*)W)[i];
        sth4(Wh + (size_t)i * 4, v);
    }
    if (i == 0) {
        g_count = 0;
        int acc = 0;
        for (int k = 0; k < 128; k++) acc |= ei32[2 * k + 1];
        g_is64 = (acc == 0) ? 1 : 0;
    }
}

__device__ __forceinline__ int load_idx(const int* ei32, long long pos, int is64) {
    return is64 ? ei32[2 * pos] : ei32[pos];
}

// ---------------- in-degree count ----------------
__global__ void deg_count(const int* __restrict__ ei32, int* __restrict__ cnt) {
    int e = blockIdx.x * 256 + threadIdx.x;
    if (e < N_EDGES) {
        int d = load_idx(ei32, (long long)N_EDGES + e, g_is64);
        if ((unsigned)d < N_NODES) atomicAdd(&cnt[d], 1);
    }
}

// ---------------- per-block exclusive scan of padded counts ----------------
__global__ __launch_bounds__(256) void scan_block(
    const int* __restrict__ cnt, int* __restrict__ rowloc, int* __restrict__ blocksum)
{
    __shared__ int sh[256];
    int t = threadIdx.x;
    int i = blockIdx.x * 256 + t;
    int c = (i < N_NODES) ? ((cnt[i] + 3) & ~3) : 0;
    sh[t] = c;
    __syncthreads();
    for (int d = 1; d < 256; d <<= 1) {
        int v = (t >= d) ? sh[t - d] : 0;
        __syncthreads();
        sh[t] += v;
        __syncthreads();
    }
    if (i < N_NODES) rowloc[i] = sh[t] - c;
    if (t == 255) blocksum[blockIdx.x] = sh[255];
}

// ---------------- tensor-core GEMM h0 = x @ W^T + b (overlapped branch) ----------------
#define WSTRIDE 136
__global__ __launch_bounds__(256) void gemm_hmma(
    const float* __restrict__ x, const __half* __restrict__ Wh,
    const float* __restrict__ b, __half* __restrict__ out)
{
    __shared__ __half Ws[128 * WSTRIDE];
    __shared__ float bs[128];
    const int tid = threadIdx.x;

#pragma unroll
    for (int it = 0; it < 8; it++) {
        int idx = it * 256 + tid;
        int r = idx >> 4, c = (idx & 15) * 8;
        *(uint4*)&Ws[r * WSTRIDE + c] = ((const uint4*)Wh)[idx];
    }
    if (tid < 128) bs[tid] = b[tid];
    __syncthreads();

    const int w = tid >> 5, lane = tid & 31;
    const int r  = lane >> 2;
    const int kq = (lane & 3) * 2;
    const int Rbase = blockIdx.x * 128 + w * 16;

    int row0 = Rbase + r;
    int row1 = Rbase + r + 8;
    int row0c = row0 < N_NODES ? row0 : 0;
    int row1c = row1 < N_NODES ? row1 : 0;

    float d[16][4];
#pragma unroll
    for (int nt = 0; nt < 16; nt++)
#pragma unroll
        for (int q = 0; q < 4; q++) d[nt][q] = 0.0f;

    const float* a0p = x + (size_t)row0c * HIDDEN;
    const float* a1p = x + (size_t)row1c * HIDDEN;

    float2 f0 = *(const float2*)(a0p + kq);
    float2 f1 = *(const float2*)(a1p + kq);
    float2 f2 = *(const float2*)(a0p + kq + 8);
    float2 f3 = *(const float2*)(a1p + kq + 8);

#pragma unroll
    for (int ks = 0; ks < 8; ks++) {
        unsigned a0 = f2h2(f0.x, f0.y);
        unsigned a1 = f2h2(f1.x, f1.y);
        unsigned a2 = f2h2(f2.x, f2.y);
        unsigned a3 = f2h2(f3.x, f3.y);
        if (ks < 7) {
            int k0 = (ks + 1) * 16 + kq;
            f0 = *(const float2*)(a0p + k0);
            f1 = *(const float2*)(a1p + k0);
            f2 = *(const float2*)(a0p + k0 + 8);
            f3 = *(const float2*)(a1p + k0 + 8);
        }
#pragma unroll
        for (int nt = 0; nt < 16; nt++) {
            int c = nt * 8 + r;
            unsigned b0 = *(const unsigned*)&Ws[c * WSTRIDE + ks * 16 + kq];
            unsigned b1 = *(const unsigned*)&Ws[c * WSTRIDE + ks * 16 + kq + 8];
            asm volatile(
                "mma.sync.aligned.m16n8k16.row.col.f32.f16.f16.f32 "
                "{%0,%1,%2,%3}, {%4,%5,%6,%7}, {%8,%9}, {%0,%1,%2,%3};"
                : "+f"(d[nt][0]), "+f"(d[nt][1]), "+f"(d[nt][2]), "+f"(d[nt][3])
                : "r"(a0), "r"(a1), "r"(a2), "r"(a3), "r"(b0), "r"(b1));
        }
    }

    const int c0 = (lane & 3) * 2;
#pragma unroll
    for (int nt = 0; nt < 16; nt++) {
        int col = nt * 8 + c0;
        if (row0 < N_NODES) {
            __half2 v = __floats2half2_rn(d[nt][0] + bs[col], d[nt][1] + bs[col + 1]);
            *(__half2*)&out[(size_t)row0 * HIDDEN + col] = v;
        }
        if (row1 < N_NODES) {
            __half2 v = __floats2half2_rn(d[nt][2] + bs[col], d[nt][3] + bs[col + 1]);
            *(__half2*)&out[(size_t)row1 * HIDDEN + col] = v;
        }
    }
}

// ---------------- scan of 391 block sums ----------------
__global__ __launch_bounds__(512) void scan_top(
    const int* __restrict__ blocksum, int* __restrict__ blockoff)
{
    __shared__ int sh[512];
    int t = threadIdx.x;
    int v = (t < NBLK_N) ? blocksum[t] : 0;
    sh[t] = v;
    __syncthreads();
    for (int d = 1; d < 512; d <<= 1) {
        int u = (t >= d) ? sh[t - d] : 0;
        __syncthreads();
        sh[t] += u;
        __syncthreads();
    }
    if (t < NBLK_N) blockoff[t] = sh[t] - v;
}

// ---------------- apply offsets + node prep + write pad slots ----------------
__global__ void prep_apply(const int* __restrict__ cnt, const int* __restrict__ rowloc,
                           const int* __restrict__ blockoff,
                           int* __restrict__ row_ptr, int* __restrict__ cursor,
                           float* __restrict__ dinv, float* __restrict__ selfw,
                           int2* __restrict__ edge)
{
    int i = blockIdx.x * 256 + threadIdx.x;
    if (i < N_NODES) {
        int c = cnt[i];
        int pad = (c + 3) & ~3;
        int beg = rowloc[i] + blockoff[blockIdx.x];
        row_ptr[i] = beg;
        cursor[i]  = beg;
        for (int k = c; k < pad; k++) edge[beg + k] = make_int2(0, 0);
        float r = rsqrtf((float)c + 1.0f);
        dinv[i]  = r;
        selfw[i] = (1.0f - ALPHA) * r * r;
        if (i == N_NODES - 1) row_ptr[N_NODES] = beg + pad;
    }
}

// ---------------- CSR edge placement ----------------
__global__ void edge_place(const int* __restrict__ ei32, const float* __restrict__ dinv,
                           int* __restrict__ cursor, int2* __restrict__ edge)
{
    int e = blockIdx.x * 256 + threadIdx.x;
    if (e < N_EDGES) {
        int is64 = g_is64;
        int s = load_idx(ei32, e, is64);
        int d = load_idx(ei32, (long long)N_EDGES + e, is64);
        if ((unsigned)s >= N_NODES) s = 0;
        if ((unsigned)d >= N_NODES) d = 0;
        int pos = atomicAdd(&cursor[d], 1);
        float w = (1.0f - ALPHA) * dinv[s] * dinv[d];
        edge[pos] = make_int2(s, __float_as_int(w));
    }
}

// ---------------- flat grid barrier (sense-reversing, generation-based) ----------------
__device__ __forceinline__ void grid_bar(int nblocks) {
    __syncthreads();
    if (threadIdx.x == 0) {
        __threadfence();                       // release this block's stores
        unsigned gen = g_sense;
        unsigned t = atomicAdd(&g_count, 1u);
        if (t == (unsigned)nblocks - 1) {
            atomicExch(&g_count, 0u);
            __threadfence();
            g_sense = gen + 1;
        } else {
            while (g_sense == gen) __nanosleep(64);
        }
        __threadfence();                       // acquire
    }
    __syncthreads();
}

// ---------------- one-hop body ----------------
// FIRST: cur == h0, fold alpha*h0 into the self term (skip one 25.6MB read)
template <bool FIRST, bool FINAL>
__device__ __forceinline__ void prop_group(
    int n, int l, const __half* __restrict__ cur, const __half* __restrict__ h0,
    const float* __restrict__ selfw, const int* __restrict__ row_ptr,
    const int2* __restrict__ edge, void* __restrict__ outp)
{
    const size_t off = (size_t)n * HIDDEN + l * 8;
    float4 svL, svH;
    ldh8(cur + off, svL, svH);
    float sw = selfw[n];

    float4 aL, aH;
    if (FIRST) {
        float c = ALPHA + sw;   // cur == h0 on hop 0
        aL.x = c * svL.x;  aL.y = c * svL.y;  aL.z = c * svL.z;  aL.w = c * svL.w;
        aH.x = c * svH.x;  aH.y = c * svH.y;  aH.z = c * svH.z;  aH.w = c * svH.w;
    } else {
        float4 h0L, h0H;
        ldh8(h0 + off, h0L, h0H);
        aL.x = ALPHA * h0L.x + sw * svL.x;  aL.y = ALPHA * h0L.y + sw * svL.y;
        aL.z = ALPHA * h0L.z + sw * svL.z;  aL.w = ALPHA * h0L.w + sw * svL.w;
        aH.x = ALPHA * h0H.x + sw * svH.x;  aH.y = ALPHA * h0H.y + sw * svH.y;
        aH.z = ALPHA * h0H.z + sw * svH.z;  aH.w = ALPHA * h0H.w + sw * svH.w;
    }

    int beg = __ldg(row_ptr + n);
    int end = __ldg(row_ptr + n + 1);   // padded end; pads = {0, 0.0f}
    for (int j = beg; j < end; j += 4) {
        const int4* ep = (const int4*)(edge + j);
        int4 E0 = __ldg(ep);
        int4 E1 = __ldg(ep + 1);
        float4 v0L,v0H,v1L,v1H,v2L,v2H,v3L,v3H;
        ldh8(cur + (size_t)E0.x * HIDDEN + l * 8, v0L, v0H);
        ldh8(cur + (size_t)E0.z * HIDDEN + l * 8, v1L, v1H);
        ldh8(cur + (size_t)E1.x * HIDDEN + l * 8, v2L, v2H);
        ldh8(cur + (size_t)E1.z * HIDDEN + l * 8, v3L, v3H);
        fma8(aL, aH, __int_as_float(E0.y), v0L, v0H);
        fma8(aL, aH, __int_as_float(E0.w), v1L, v1H);
        fma8(aL, aH, __int_as_float(E1.y), v2L, v2H);
        fma8(aL, aH, __int_as_float(E1.w), v3L, v3H);
    }

    if (FINAL) {
        float* o = (float*)outp + off;
        *(float4*)o       = aL;
        *(float4*)(o + 4) = aH;
    } else {
        __half* o = (__half*)outp + off;
        sth4(o, aL);
        sth4(o + 4, aH);
    }
}

// ---------------- persistent prop: all KHOPS in one launch ----------------
__global__ __launch_bounds__(256) void prop_persist(
    const __half* __restrict__ h0, __half* __restrict__ bufA, __half* __restrict__ bufB,
    const float* __restrict__ selfw, const int* __restrict__ row_ptr,
    const int2* __restrict__ edge, float* __restrict__ out, int nblocks)
{
    const int NLANES = N_NODES * 16;
    const int stride = nblocks * 256;
    int base = blockIdx.x * 256 + threadIdx.x;

    for (int hop = 0; hop < KHOPS; hop++) {
        const __half* cur = (hop == 0) ? h0 : ((hop & 1) ? bufA : bufB);
        for (int gtid = base; gtid < NLANES; gtid += stride) {
            int n = gtid >> 4, l = gtid & 15;
            if (hop == 0)
                prop_group<true, false>(n, l, cur, h0, selfw, row_ptr, edge, bufA);
            else if (hop == KHOPS - 1)
                prop_group<false, true >(n, l, cur, h0, selfw, row_ptr, edge, out);
            else
                prop_group<false, false>(n, l, cur, h0, selfw, row_ptr, edge,
                                         (hop & 1) ? bufB : bufA);
        }
        if (hop < KHOPS - 1) grid_bar(nblocks);
    }
}

// ---------------- fallback per-hop kernel ----------------
template <bool FIRST, bool FINAL>
__global__ __launch_bounds__(256) void prop_kernel(
    const __half* __restrict__ cur, const __half* __restrict__ h0,
    const float* __restrict__ selfw,
    const int* __restrict__ row_ptr, const int2* __restrict__ edge,
    void* __restrict__ outp)
{
    int gtid = blockIdx.x * 256 + threadIdx.x;
    int n = gtid >> 4, l = gtid & 15;
    if (n >= N_NODES) return;
    prop_group<FIRST, FINAL>(n, l, cur, h0, selfw, row_ptr, edge, outp);
}

// ---------------- launch ----------------
extern "C" void kernel_launch(void* const* d_in, const int* in_sizes, int n_in,
                              void* d_out, int out_size)
{
    const float* x    = (const float*)d_in[0];
    const int*   ei32 = (const int*)d_in[1];
    const float* W    = (const float*)d_in[2];
    const float* b    = (const float*)d_in[3];
    float* out = (float*)d_out;

    __half *Wh, *h0h, *bufA, *bufB;
    float *dinv, *selfw;
    int *cnt, *rowloc, *blocksum, *blockoff, *row_ptr, *cursor;
    int2 *edge;
    cudaGetSymbolAddress((void**)&Wh,       g_Wh);
    cudaGetSymbolAddress((void**)&h0h,      g_h0h);
    cudaGetSymbolAddress((void**)&bufA,     g_bufA);
    cudaGetSymbolAddress((void**)&bufB,     g_bufB);
    cudaGetSymbolAddress((void**)&cnt,      g_cnt);
    cudaGetSymbolAddress((void**)&rowloc,   g_rowloc);
    cudaGetSymbolAddress((void**)&blocksum, g_blocksum);
    cudaGetSymbolAddress((void**)&blockoff, g_blockoff);
    cudaGetSymbolAddress((void**)&row_ptr,  g_rowptr);
    cudaGetSymbolAddress((void**)&cursor,   g_cursor);
    cudaGetSymbolAddress((void**)&dinv,     g_dinv);
    cudaGetSymbolAddress((void**)&selfw,    g_selfw);
    cudaGetSymbolAddress((void**)&edge,     g_edge);

    const int NB_E = (N_EDGES + 255) / 256;   // 2344
    const int NB_G = (N_NODES + 127) / 128;   // 782

    cudaStream_t s2;
    cudaEvent_t evFork, evJoin;
    cudaStreamCreateWithFlags(&s2, cudaStreamNonBlocking);
    cudaEventCreateWithFlags(&evFork, cudaEventDisableTiming);
    cudaEventCreateWithFlags(&evJoin, cudaEventDisableTiming);

    probe_zero<<<NBLK_N, 256>>>(ei32, W, cnt, Wh);

    // fork: GEMM runs in parallel with the CSR build
    cudaEventRecord(evFork, 0);
    cudaStreamWaitEvent(s2, evFork, 0);
    gemm_hmma<<<NB_G, 256, 0, s2>>>(x, Wh, b, h0h);

    deg_count <<<NB_E, 256>>>(ei32, cnt);
    scan_block<<<NBLK_N, 256>>>(cnt, rowloc, blocksum);
    scan_top  <<<1, 512>>>(blocksum, blockoff);
    prep_apply<<<NBLK_N, 256>>>(cnt, rowloc, blockoff, row_ptr, cursor,
                                dinv, selfw, edge);
    edge_place<<<NB_E, 256>>>(ei32, dinv, cursor, edge);

    cudaEventRecord(evJoin, s2);
    cudaStreamWaitEvent(0, evJoin, 0);

    // persistent prop sized to guaranteed co-residency
    int perSM = 0, sms = 0, dev = 0;
    cudaGetDevice(&dev);
    cudaDeviceGetAttribute(&sms, cudaDevAttrMultiProcessorCount, dev);
    cudaOccupancyMaxActiveBlocksPerMultiprocessor(&perSM, prop_persist, 256, 0);

    if (perSM > 0 && sms > 0) {
        int nblocks = perSM * sms;
        const int maxblocks = (N_NODES * 16 + 255) / 256;  // no more than the work
        if (nblocks > maxblocks) nblocks = maxblocks;
        prop_persist<<<nblocks, 256>>>(h0h, bufA, bufB, selfw, row_ptr, edge, out, nblocks);
    } else {
        const int NB_PROP = (N_NODES * 16 + 255) / 256;
        const __half* cur = h0h;
        for (int hop = 0; hop < KHOPS; hop++) {
            if (hop == 0) {
                prop_kernel<true, false><<<NB_PROP, 256>>>(cur, h0h, selfw, row_ptr, edge, bufA);
                cur = bufA;
            } else if (hop == KHOPS - 1) {
                prop_kernel<false, true><<<NB_PROP, 256>>>(cur, h0h, selfw, row_ptr, edge, out);
            } else {
                __half* nxt = (hop & 1) ? bufB : bufA;
                prop_kernel<false, false><<<NB_PROP, 256>>>(cur, h0h, selfw, row_ptr, edge, nxt);
                cur = nxt;
            }
        }
    }
}